// round 5
// baseline (speedup 1.0000x reference)
#include <cuda_runtime.h>

namespace {

constexpr int BATCH = 16;
constexpr int DIM   = 48;
constexpr int HID   = 16;
constexpr int CC    = 8;          // gated half
constexpr int Hh    = 256;
constexpr int Ww    = 256;
constexpr int HW    = Hh * Ww;
constexpr int TH    = 32;
constexpr int TW    = 32;
constexpr int PTH   = TH + 2;     // 34
constexpr int PTW   = TW + 2;     // 34
constexpr int NPAD  = PTH * PTW;  // 1156
constexpr int NINT  = TH * TW;    // 1024
constexpr int THREADS = 256;
constexpr float LN_EPS = 1e-5f;

__device__ __forceinline__ float gelu_f(float v) {
    return 0.5f * v * (1.0f + erff(v * 0.70710678118654752440f));
}

// computes 8 hidden channels [jbase, jbase+8) of the front GEMM for one token
__device__ __forceinline__ void gemm8(const float4* __restrict__ xp,
                                      const float* __restrict__ sW1,
                                      const float* __restrict__ sb1,
                                      int jbase, float y[CC]) {
    #pragma unroll
    for (int j = 0; j < CC; ++j) y[j] = sb1[jbase + j];
    #pragma unroll
    for (int d4 = 0; d4 < DIM / 4; ++d4) {
        const float4 xv = __ldg(xp + d4);
        const float xs[4] = {xv.x, xv.y, xv.z, xv.w};
        #pragma unroll
        for (int k = 0; k < 4; ++k) {
            const int d = d4 * 4 + k;
            const float4* w4 = (const float4*)(sW1 + d * HID + jbase);
            const float4 a0 = w4[0], a1 = w4[1];
            const float xvk = xs[k];
            y[0] = fmaf(xvk, a0.x, y[0]);  y[1] = fmaf(xvk, a0.y, y[1]);
            y[2] = fmaf(xvk, a0.z, y[2]);  y[3] = fmaf(xvk, a0.w, y[3]);
            y[4] = fmaf(xvk, a1.x, y[4]);  y[5] = fmaf(xvk, a1.y, y[5]);
            y[6] = fmaf(xvk, a1.z, y[6]);  y[7] = fmaf(xvk, a1.w, y[7]);
        }
    }
    #pragma unroll
    for (int j = 0; j < CC; ++j) y[j] = gelu_f(gelu_f(y[j]));
}

__global__ __launch_bounds__(THREADS, 2)
void fused_block(const float* __restrict__ x,
                 const float* __restrict__ gW1, const float* __restrict__ gb1,
                 const float* __restrict__ ggamma, const float* __restrict__ gbeta,
                 const float* __restrict__ gdww, const float* __restrict__ gdwb,
                 const float* __restrict__ gpww, const float* __restrict__ gpwb,
                 const float* __restrict__ gW2, const float* __restrict__ gb2,
                 float* __restrict__ out)
{
    __shared__ __align__(16) float sW1[DIM * HID];   // [d][j]
    __shared__ __align__(16) float sW2[CC * DIM];    // [c][d]
    __shared__ __align__(16) float sb2[DIM];
    __shared__ float sb1[HID];
    __shared__ float sPw[CC * CC];                   // [cout][cin]
    __shared__ float sPwb[CC];
    __shared__ float sDw[CC * 9];                    // [c][ky*3+kx]
    __shared__ float sDwb[CC];
    __shared__ float sG[CC];
    __shared__ float sBt[CC];

    extern __shared__ float dyn[];
    float* sN  = dyn;                 // CC planes of NPAD (layernormed x2, halo'd)
    float* sX1 = dyn + CC * NPAD;     // CC planes of NINT (gate input)

    const int tid = threadIdx.x;
    for (int i = tid; i < DIM * HID; i += THREADS) sW1[i] = gW1[i];
    for (int i = tid; i < CC * DIM;  i += THREADS) sW2[i] = gW2[i];
    if (tid < CC * 9) sDw[tid] = gdww[tid];
    if (tid < HID)    sb1[tid] = gb1[tid];
    if (tid < DIM)    sb2[tid] = gb2[tid];
    if (tid < CC * CC) sPw[tid] = gpww[tid];
    if (tid < CC) {
        sPwb[tid] = gpwb[tid];
        sDwb[tid] = gdwb[tid];
        sG[tid]   = ggamma[tid];
        sBt[tid]  = gbeta[tid];
    }

    const int b  = blockIdx.z;
    const int h0 = blockIdx.y * TH;
    const int w0 = blockIdx.x * TW;
    const float* xb = x + (size_t)b * DIM * HW;     // tokens: 48 contiguous floats

    __syncthreads();

    // ---- Pass A: x2 half over halo'd tile -> double GELU -> LN -> sN ----
    #pragma unroll 1
    for (int p = tid; p < NPAD; p += THREADS) {
        const int py = p / PTW;
        const int px = p - py * PTW;
        const int gh = h0 + py - 1;
        const int gw = w0 + px - 1;

        if ((unsigned)gh >= (unsigned)Hh || (unsigned)gw >= (unsigned)Ww) {
            #pragma unroll
            for (int c = 0; c < CC; ++c) sN[c * NPAD + p] = 0.0f;
            continue;
        }

        float y[CC];
        gemm8((const float4*)(xb + (size_t)(gh * Ww + gw) * DIM), sW1, sb1, CC, y);

        // LayerNorm over the 8 x2 channels
        float m = 0.0f;
        #pragma unroll
        for (int c = 0; c < CC; ++c) m += y[c];
        m *= 0.125f;
        float var = 0.0f;
        #pragma unroll
        for (int c = 0; c < CC; ++c) { const float dd = y[c] - m; var = fmaf(dd, dd, var); }
        const float inv = rsqrtf(var * 0.125f + LN_EPS);

        #pragma unroll
        for (int c = 0; c < CC; ++c)
            sN[c * NPAD + p] = (y[c] - m) * inv * sG[c] + sBt[c];
    }

    // ---- Pass B: x1 half over interior -> double GELU -> sX1 ----
    #pragma unroll 1
    for (int q = tid; q < NINT; q += THREADS) {
        const int ty = q >> 5;
        const int tx = q & 31;
        const int gh = h0 + ty;
        const int gw = w0 + tx;

        float y[CC];
        gemm8((const float4*)(xb + (size_t)(gh * Ww + gw) * DIM), sW1, sb1, 0, y);

        #pragma unroll
        for (int c = 0; c < CC; ++c) sX1[c * NINT + q] = y[c];
    }

    __syncthreads();

    // ---------------- Phase 2: dw 3x3 + pw 1x1 + gate + GEMM 8->48 ----------------
    float* ob = out + (size_t)b * DIM * HW;
    #pragma unroll 1
    for (int q = tid; q < NINT; q += THREADS) {
        const int ty = q >> 5;
        const int tx = q & 31;
        const int py = ty + 1;
        const int px = tx + 1;

        float ncen[CC];
        #pragma unroll
        for (int c = 0; c < CC; ++c) ncen[c] = sN[c * NPAD + py * PTW + px];

        float g[CC];
        #pragma unroll
        for (int c = 0; c < CC; ++c) {
            const float* nb = sN + c * NPAD;
            const float* k9 = sDw + c * 9;
            float acc = sDwb[c];
            #pragma unroll
            for (int dy = 0; dy < 3; ++dy) {
                const float* r = nb + (py - 1 + dy) * PTW + (px - 1);
                acc = fmaf(r[0], k9[dy * 3 + 0], acc);
                acc = fmaf(r[1], k9[dy * 3 + 1], acc);
                acc = fmaf(r[2], k9[dy * 3 + 2], acc);
            }
            float chv = sPwb[c];
            #pragma unroll
            for (int cin = 0; cin < CC; ++cin)
                chv = fmaf(ncen[cin], sPw[c * CC + cin], chv);
            g[c] = sX1[c * NINT + q] * acc * chv;
        }

        // out[d] = sum_c g[c]*W2[c][d] + b2[d]; NCHW scatter (coalesced per d across warp)
        float* op = ob + (h0 + ty) * Ww + (w0 + tx);
        #pragma unroll
        for (int d4 = 0; d4 < DIM / 4; ++d4) {
            float4 acc = *(const float4*)(sb2 + d4 * 4);
            #pragma unroll
            for (int c = 0; c < CC; ++c) {
                const float4 wv = *(const float4*)(sW2 + c * DIM + d4 * 4);
                const float gc = g[c];
                acc.x = fmaf(gc, wv.x, acc.x);
                acc.y = fmaf(gc, wv.y, acc.y);
                acc.z = fmaf(gc, wv.z, acc.z);
                acc.w = fmaf(gc, wv.w, acc.w);
            }
            op[(size_t)(d4 * 4 + 0) * HW] = acc.x;
            op[(size_t)(d4 * 4 + 1) * HW] = acc.y;
            op[(size_t)(d4 * 4 + 2) * HW] = acc.z;
            op[(size_t)(d4 * 4 + 3) * HW] = acc.w;
        }
    }
}

} // namespace

extern "C" void kernel_launch(void* const* d_in, const int* in_sizes, int n_in,
                              void* d_out, int out_size) {
    const float* x     = (const float*)d_in[0];
    const float* W1    = (const float*)d_in[1];
    const float* b1    = (const float*)d_in[2];
    const float* gamma = (const float*)d_in[3];
    const float* beta  = (const float*)d_in[4];
    const float* dw_w  = (const float*)d_in[5];
    const float* dw_b  = (const float*)d_in[6];
    const float* pw_w  = (const float*)d_in[7];
    const float* pw_b  = (const float*)d_in[8];
    const float* W2    = (const float*)d_in[9];
    const float* b2    = (const float*)d_in[10];
    float* out = (float*)d_out;

    const int shmem = (CC * NPAD + CC * NINT) * (int)sizeof(float); // 69760 B
    cudaFuncSetAttribute(fused_block, cudaFuncAttributeMaxDynamicSharedMemorySize, shmem);

    dim3 grid(Ww / TW, Hh / TH, BATCH);
    fused_block<<<grid, THREADS, shmem>>>(x, W1, b1, gamma, beta,
                                          dw_w, dw_b, pw_w, pw_b, W2, b2, out);
}

// round 6
// speedup vs baseline: 3.8933x; 3.8933x over previous
#include <cuda_runtime.h>

namespace {

constexpr int BATCH = 16;
constexpr int DIM   = 48;
constexpr int HID   = 16;
constexpr int CC    = 8;
constexpr int Hh    = 256;
constexpr int Ww    = 256;
constexpr int HW    = Hh * Ww;
constexpr float LN_EPS = 1e-5f;
constexpr int THREADS = 256;

// intermediate: per batch 16 planes of HW floats; ch 0..7 = x1 (gate), 8..15 = LN(x2)
__device__ float g_mid[(size_t)BATCH * HID * HW];

__device__ __forceinline__ float gelu_f(float v) {
    return 0.5f * v * (1.0f + erff(v * 0.70710678118654752440f));
}

// ---------------- Kernel 1: token GEMM 48->16, double GELU, LN ----------------
__global__ __launch_bounds__(THREADS, 2)
void k_front(const float* __restrict__ x,
             const float* __restrict__ gW1, const float* __restrict__ gb1,
             const float* __restrict__ ggamma, const float* __restrict__ gbeta)
{
    __shared__ __align__(16) float sW1[DIM * HID];
    __shared__ float sb1[HID];
    __shared__ float sG[CC], sBt[CC];

    const int tid = threadIdx.x;
    for (int i = tid; i < DIM * HID; i += THREADS) sW1[i] = gW1[i];
    if (tid < HID) sb1[tid] = gb1[tid];
    if (tid < CC)  { sG[tid] = ggamma[tid]; sBt[tid] = gbeta[tid]; }
    __syncthreads();

    const int t = blockIdx.x * THREADS + tid;          // token id = b*HW + pix
    const float* xt = x + (size_t)t * DIM;             // 48 contiguous floats

    float y[HID];
    #pragma unroll
    for (int j = 0; j < HID; ++j) y[j] = sb1[j];

    #pragma unroll 1
    for (int ch = 0; ch < 3; ++ch) {                   // 16 input dims per chunk
        const float4* xp = (const float4*)(xt + ch * 16);
        const float4 v0 = __ldg(xp + 0), v1 = __ldg(xp + 1),
                     v2 = __ldg(xp + 2), v3 = __ldg(xp + 3);
        const float xs[16] = {v0.x, v0.y, v0.z, v0.w, v1.x, v1.y, v1.z, v1.w,
                              v2.x, v2.y, v2.z, v2.w, v3.x, v3.y, v3.z, v3.w};
        #pragma unroll
        for (int k = 0; k < 16; ++k) {
            const int d = ch * 16 + k;
            const float4* w4 = (const float4*)(sW1 + d * HID);  // uniform -> smem broadcast
            const float4 a0 = w4[0], a1 = w4[1], a2 = w4[2], a3 = w4[3];
            const float xv = xs[k];
            y[0]  = fmaf(xv, a0.x, y[0]);   y[1]  = fmaf(xv, a0.y, y[1]);
            y[2]  = fmaf(xv, a0.z, y[2]);   y[3]  = fmaf(xv, a0.w, y[3]);
            y[4]  = fmaf(xv, a1.x, y[4]);   y[5]  = fmaf(xv, a1.y, y[5]);
            y[6]  = fmaf(xv, a1.z, y[6]);   y[7]  = fmaf(xv, a1.w, y[7]);
            y[8]  = fmaf(xv, a2.x, y[8]);   y[9]  = fmaf(xv, a2.y, y[9]);
            y[10] = fmaf(xv, a2.z, y[10]);  y[11] = fmaf(xv, a2.w, y[11]);
            y[12] = fmaf(xv, a3.x, y[12]);  y[13] = fmaf(xv, a3.y, y[13]);
            y[14] = fmaf(xv, a3.z, y[14]);  y[15] = fmaf(xv, a3.w, y[15]);
        }
    }

    #pragma unroll
    for (int j = 0; j < HID; ++j) y[j] = gelu_f(gelu_f(y[j]));

    // LayerNorm over y[8..15]
    float m = 0.0f;
    #pragma unroll
    for (int c = 0; c < CC; ++c) m += y[CC + c];
    m *= 0.125f;
    float var = 0.0f;
    #pragma unroll
    for (int c = 0; c < CC; ++c) { const float dd = y[CC + c] - m; var = fmaf(dd, dd, var); }
    const float inv = rsqrtf(var * 0.125f + LN_EPS);

    const int b   = t >> 16;
    const int pix = t & (HW - 1);
    float* mb = g_mid + ((size_t)b * HID) * HW + pix;
    #pragma unroll
    for (int c = 0; c < CC; ++c) mb[(size_t)c * HW] = y[c];
    #pragma unroll
    for (int c = 0; c < CC; ++c)
        mb[(size_t)(CC + c) * HW] = (y[CC + c] - m) * inv * sG[c] + sBt[c];
}

// ---------------- Kernel 2: dw3x3 + pw1x1 + gate + GEMM 8->48 ----------------
constexpr int TH2 = 8;
constexpr int TW2 = 32;
constexpr int PH2 = TH2 + 2;   // 10
constexpr int PW2 = TW2 + 2;   // 34
constexpr int NT2 = PH2 * PW2; // 340

__global__ __launch_bounds__(THREADS, 3)
void k_back(const float* __restrict__ gdww, const float* __restrict__ gdwb,
            const float* __restrict__ gpww, const float* __restrict__ gpwb,
            const float* __restrict__ gW2, const float* __restrict__ gb2,
            float* __restrict__ out)
{
    __shared__ float sTile[CC][NT2];                 // LN'd x2, halo'd
    __shared__ __align__(16) float sW2[CC * DIM];
    __shared__ __align__(16) float sb2[DIM];
    __shared__ float sPw[CC * CC], sPwb[CC];
    __shared__ float sDw[CC * 9], sDwb[CC];

    const int tid = threadIdx.x;
    for (int i = tid; i < CC * DIM; i += THREADS) sW2[i] = gW2[i];
    if (tid < DIM)     sb2[tid] = gb2[tid];
    if (tid < CC * CC) sPw[tid] = gpww[tid];
    if (tid < CC * 9)  sDw[tid] = gdww[tid];
    if (tid < CC)      { sPwb[tid] = gpwb[tid]; sDwb[tid] = gdwb[tid]; }

    const int b  = blockIdx.z;
    const int h0 = blockIdx.y * TH2;
    const int w0 = blockIdx.x * TW2;

    const float* nb = g_mid + ((size_t)b * HID + CC) * HW;   // planes 8..15

    // cooperative halo'd tile load (zero padding outside image)
    #pragma unroll 1
    for (int i = tid; i < CC * NT2; i += THREADS) {
        const int c   = i / NT2;
        const int rem = i - c * NT2;
        const int py  = rem / PW2;
        const int px  = rem - py * PW2;
        const int gh  = h0 + py - 1;
        const int gw  = w0 + px - 1;
        float v = 0.0f;
        if ((unsigned)gh < (unsigned)Hh && (unsigned)gw < (unsigned)Ww)
            v = nb[(size_t)c * HW + gh * Ww + gw];
        sTile[c][rem] = v;
    }
    __syncthreads();

    const int ty = tid >> 5;
    const int tx = tid & 31;
    const int py = ty + 1;
    const int px = tx + 1;
    const int pix = (h0 + ty) * Ww + (w0 + tx);

    float ncen[CC];
    #pragma unroll
    for (int c = 0; c < CC; ++c) ncen[c] = sTile[c][py * PW2 + px];

    const float* x1b = g_mid + ((size_t)b * HID) * HW + pix;

    float g[CC];
    #pragma unroll
    for (int c = 0; c < CC; ++c) {
        const float* tp = sTile[c];
        const float* k9 = sDw + c * 9;
        float acc = sDwb[c];
        #pragma unroll
        for (int dy = 0; dy < 3; ++dy) {
            const float* r = tp + (py - 1 + dy) * PW2 + (px - 1);
            acc = fmaf(r[0], k9[dy * 3 + 0], acc);
            acc = fmaf(r[1], k9[dy * 3 + 1], acc);
            acc = fmaf(r[2], k9[dy * 3 + 2], acc);
        }
        float chv = sPwb[c];
        #pragma unroll
        for (int cin = 0; cin < CC; ++cin)
            chv = fmaf(ncen[cin], sPw[c * CC + cin], chv);
        g[c] = __ldg(x1b + (size_t)c * HW) * acc * chv;
    }

    float* op = out + (size_t)b * DIM * HW + pix;
    #pragma unroll
    for (int d4 = 0; d4 < DIM / 4; ++d4) {
        float4 acc = *(const float4*)(sb2 + d4 * 4);
        #pragma unroll
        for (int c = 0; c < CC; ++c) {
            const float4 wv = *(const float4*)(sW2 + c * DIM + d4 * 4);
            const float gc = g[c];
            acc.x = fmaf(gc, wv.x, acc.x);
            acc.y = fmaf(gc, wv.y, acc.y);
            acc.z = fmaf(gc, wv.z, acc.z);
            acc.w = fmaf(gc, wv.w, acc.w);
        }
        op[(size_t)(d4 * 4 + 0) * HW] = acc.x;
        op[(size_t)(d4 * 4 + 1) * HW] = acc.y;
        op[(size_t)(d4 * 4 + 2) * HW] = acc.z;
        op[(size_t)(d4 * 4 + 3) * HW] = acc.w;
    }
}

} // namespace

extern "C" void kernel_launch(void* const* d_in, const int* in_sizes, int n_in,
                              void* d_out, int out_size) {
    const float* x     = (const float*)d_in[0];
    const float* W1    = (const float*)d_in[1];
    const float* b1    = (const float*)d_in[2];
    const float* gamma = (const float*)d_in[3];
    const float* beta  = (const float*)d_in[4];
    const float* dw_w  = (const float*)d_in[5];
    const float* dw_b  = (const float*)d_in[6];
    const float* pw_w  = (const float*)d_in[7];
    const float* pw_b  = (const float*)d_in[8];
    const float* W2    = (const float*)d_in[9];
    const float* b2    = (const float*)d_in[10];
    float* out = (float*)d_out;

    k_front<<<BATCH * HW / THREADS, THREADS>>>(x, W1, b1, gamma, beta);

    dim3 grid2(Ww / TW2, Hh / TH2, BATCH);
    k_back<<<grid2, THREADS>>>(dw_w, dw_b, pw_w, pw_b, W2, b2, out);
}

// round 7
// speedup vs baseline: 4.0778x; 1.0474x over previous
#include <cuda_runtime.h>

namespace {

constexpr int BATCH = 16;
constexpr int DIM   = 48;
constexpr int HID   = 16;
constexpr int CC    = 8;
constexpr int Hh    = 256;
constexpr int Ww    = 256;
constexpr int HW    = Hh * Ww;
constexpr float LN_EPS = 1e-5f;
constexpr int THREADS = 256;
constexpr int XSTRIDE = 52;   // padded token stride in smem floats (16B-aligned, bank-friendly)

// intermediate: per batch 16 planes of HW floats; ch 0..7 = x1 (gate), 8..15 = LN(x2)
__device__ float g_mid[(size_t)BATCH * HID * HW];

__device__ __forceinline__ float gelu_f(float v) {
    return 0.5f * v * (1.0f + erff(v * 0.70710678118654752440f));
}

// ---------------- Kernel 1: token GEMM 48->16, double GELU, LN ----------------
__global__ __launch_bounds__(THREADS, 2)
void k_front(const float* __restrict__ x,
             const float* __restrict__ gW1, const float* __restrict__ gb1,
             const float* __restrict__ ggamma, const float* __restrict__ gbeta)
{
    __shared__ __align__(16) float sW1[DIM * HID];
    __shared__ float sb1[HID];
    __shared__ float sG[CC], sBt[CC];
    extern __shared__ __align__(16) float sX[];      // 256 tokens * 52 floats

    const int tid = threadIdx.x;
    for (int i = tid; i < DIM * HID; i += THREADS) sW1[i] = gW1[i];
    if (tid < HID) sb1[tid] = gb1[tid];
    if (tid < CC)  { sG[tid] = ggamma[tid]; sBt[tid] = gbeta[tid]; }

    // coalesced stage: this block's 256 tokens (256*48 floats) as float4
    const float4* xg4 = (const float4*)x;
    const size_t base4 = (size_t)blockIdx.x * THREADS * (DIM / 4);
    #pragma unroll 4
    for (int i = tid; i < THREADS * (DIM / 4); i += THREADS) {
        const int tok = i / (DIM / 4);
        const int e4  = i - tok * (DIM / 4);
        *(float4*)(sX + tok * XSTRIDE + e4 * 4) = xg4[base4 + i];
    }
    __syncthreads();

    const int t = blockIdx.x * THREADS + tid;          // token id = b*HW + pix
    const float4* xp = (const float4*)(sX + tid * XSTRIDE);

    float y[HID];
    #pragma unroll
    for (int j = 0; j < HID; ++j) y[j] = sb1[j];

    #pragma unroll 1
    for (int ch = 0; ch < 3; ++ch) {                   // 16 input dims per chunk
        const float4 v0 = xp[ch * 4 + 0], v1 = xp[ch * 4 + 1],
                     v2 = xp[ch * 4 + 2], v3 = xp[ch * 4 + 3];
        const float xs[16] = {v0.x, v0.y, v0.z, v0.w, v1.x, v1.y, v1.z, v1.w,
                              v2.x, v2.y, v2.z, v2.w, v3.x, v3.y, v3.z, v3.w};
        #pragma unroll
        for (int k = 0; k < 16; ++k) {
            const int d = ch * 16 + k;
            const float4* w4 = (const float4*)(sW1 + d * HID);  // uniform -> smem broadcast
            const float4 a0 = w4[0], a1 = w4[1], a2 = w4[2], a3 = w4[3];
            const float xv = xs[k];
            y[0]  = fmaf(xv, a0.x, y[0]);   y[1]  = fmaf(xv, a0.y, y[1]);
            y[2]  = fmaf(xv, a0.z, y[2]);   y[3]  = fmaf(xv, a0.w, y[3]);
            y[4]  = fmaf(xv, a1.x, y[4]);   y[5]  = fmaf(xv, a1.y, y[5]);
            y[6]  = fmaf(xv, a1.z, y[6]);   y[7]  = fmaf(xv, a1.w, y[7]);
            y[8]  = fmaf(xv, a2.x, y[8]);   y[9]  = fmaf(xv, a2.y, y[9]);
            y[10] = fmaf(xv, a2.z, y[10]);  y[11] = fmaf(xv, a2.w, y[11]);
            y[12] = fmaf(xv, a3.x, y[12]);  y[13] = fmaf(xv, a3.y, y[13]);
            y[14] = fmaf(xv, a3.z, y[14]);  y[15] = fmaf(xv, a3.w, y[15]);
        }
    }

    #pragma unroll
    for (int j = 0; j < HID; ++j) y[j] = gelu_f(gelu_f(y[j]));

    // LayerNorm over y[8..15]
    float m = 0.0f;
    #pragma unroll
    for (int c = 0; c < CC; ++c) m += y[CC + c];
    m *= 0.125f;
    float var = 0.0f;
    #pragma unroll
    for (int c = 0; c < CC; ++c) { const float dd = y[CC + c] - m; var = fmaf(dd, dd, var); }
    const float inv = rsqrtf(var * 0.125f + LN_EPS);

    const int b   = t >> 16;
    const int pix = t & (HW - 1);
    float* mb = g_mid + ((size_t)b * HID) * HW + pix;
    #pragma unroll
    for (int c = 0; c < CC; ++c) mb[(size_t)c * HW] = y[c];
    #pragma unroll
    for (int c = 0; c < CC; ++c)
        mb[(size_t)(CC + c) * HW] = (y[CC + c] - m) * inv * sG[c] + sBt[c];
}

// ---------------- Kernel 2: dw3x3 + pw1x1 + gate + GEMM 8->48 ----------------
constexpr int TH2 = 8;
constexpr int TW2 = 32;
constexpr int PH2 = TH2 + 2;   // 10
constexpr int PW2 = TW2 + 2;   // 34
constexpr int NT2 = PH2 * PW2; // 340

__global__ __launch_bounds__(THREADS, 4)
void k_back(const float* __restrict__ gdww, const float* __restrict__ gdwb,
            const float* __restrict__ gpww, const float* __restrict__ gpwb,
            const float* __restrict__ gW2, const float* __restrict__ gb2,
            float* __restrict__ out)
{
    __shared__ float sTile[CC][NT2];                 // LN'd x2, halo'd
    __shared__ __align__(16) float sW2[CC * DIM];
    __shared__ __align__(16) float sb2[DIM];
    __shared__ float sPw[CC * CC], sPwb[CC];
    __shared__ float sDw[CC * 9], sDwb[CC];

    const int tid = threadIdx.x;
    for (int i = tid; i < CC * DIM; i += THREADS) sW2[i] = gW2[i];
    if (tid < DIM)     sb2[tid] = gb2[tid];
    if (tid < CC * CC) sPw[tid] = gpww[tid];
    if (tid < CC * 9)  sDw[tid] = gdww[tid];
    if (tid < CC)      { sPwb[tid] = gpwb[tid]; sDwb[tid] = gdwb[tid]; }

    const int b  = blockIdx.z;
    const int h0 = blockIdx.y * TH2;
    const int w0 = blockIdx.x * TW2;

    const float* nb = g_mid + ((size_t)b * HID + CC) * HW;   // planes 8..15

    // cooperative halo'd tile load (zero padding outside image)
    #pragma unroll 1
    for (int i = tid; i < CC * NT2; i += THREADS) {
        const int c   = i / NT2;
        const int rem = i - c * NT2;
        const int py  = rem / PW2;
        const int px  = rem - py * PW2;
        const int gh  = h0 + py - 1;
        const int gw  = w0 + px - 1;
        float v = 0.0f;
        if ((unsigned)gh < (unsigned)Hh && (unsigned)gw < (unsigned)Ww)
            v = nb[(size_t)c * HW + gh * Ww + gw];
        sTile[c][rem] = v;
    }
    __syncthreads();

    const int ty = tid >> 5;
    const int tx = tid & 31;
    const int py = ty + 1;
    const int px = tx + 1;
    const int pix = (h0 + ty) * Ww + (w0 + tx);

    float ncen[CC];
    #pragma unroll
    for (int c = 0; c < CC; ++c) ncen[c] = sTile[c][py * PW2 + px];

    const float* x1b = g_mid + ((size_t)b * HID) * HW + pix;

    float g[CC];
    #pragma unroll
    for (int c = 0; c < CC; ++c) {
        const float* tp = sTile[c];
        const float* k9 = sDw + c * 9;
        float acc = sDwb[c];
        #pragma unroll
        for (int dy = 0; dy < 3; ++dy) {
            const float* r = tp + (py - 1 + dy) * PW2 + (px - 1);
            acc = fmaf(r[0], k9[dy * 3 + 0], acc);
            acc = fmaf(r[1], k9[dy * 3 + 1], acc);
            acc = fmaf(r[2], k9[dy * 3 + 2], acc);
        }
        float chv = sPwb[c];
        #pragma unroll
        for (int cin = 0; cin < CC; ++cin)
            chv = fmaf(ncen[cin], sPw[c * CC + cin], chv);
        g[c] = __ldg(x1b + (size_t)c * HW) * acc * chv;
    }

    float* op = out + (size_t)b * DIM * HW + pix;
    #pragma unroll
    for (int d4 = 0; d4 < DIM / 4; ++d4) {
        float4 acc = *(const float4*)(sb2 + d4 * 4);
        #pragma unroll
        for (int c = 0; c < CC; ++c) {
            const float4 wv = *(const float4*)(sW2 + c * DIM + d4 * 4);
            const float gc = g[c];
            acc.x = fmaf(gc, wv.x, acc.x);
            acc.y = fmaf(gc, wv.y, acc.y);
            acc.z = fmaf(gc, wv.z, acc.z);
            acc.w = fmaf(gc, wv.w, acc.w);
        }
        op[(size_t)(d4 * 4 + 0) * HW] = acc.x;
        op[(size_t)(d4 * 4 + 1) * HW] = acc.y;
        op[(size_t)(d4 * 4 + 2) * HW] = acc.z;
        op[(size_t)(d4 * 4 + 3) * HW] = acc.w;
    }
}

} // namespace

extern "C" void kernel_launch(void* const* d_in, const int* in_sizes, int n_in,
                              void* d_out, int out_size) {
    const float* x     = (const float*)d_in[0];
    const float* W1    = (const float*)d_in[1];
    const float* b1    = (const float*)d_in[2];
    const float* gamma = (const float*)d_in[3];
    const float* beta  = (const float*)d_in[4];
    const float* dw_w  = (const float*)d_in[5];
    const float* dw_b  = (const float*)d_in[6];
    const float* pw_w  = (const float*)d_in[7];
    const float* pw_b  = (const float*)d_in[8];
    const float* W2    = (const float*)d_in[9];
    const float* b2    = (const float*)d_in[10];
    float* out = (float*)d_out;

    const int dyn1 = THREADS * XSTRIDE * (int)sizeof(float);   // 53248 B
    cudaFuncSetAttribute(k_front, cudaFuncAttributeMaxDynamicSharedMemorySize, dyn1);

    k_front<<<BATCH * HW / THREADS, THREADS, dyn1>>>(x, W1, b1, gamma, beta);

    dim3 grid2(Ww / TW2, Hh / TH2, BATCH);
    k_back<<<grid2, THREADS>>>(dw_w, dw_b, pw_w, pw_b, W2, b2, out);
}